// round 14
// baseline (speedup 1.0000x reference)
#include <cuda_runtime.h>
#include <cuda_fp16.h>
#include <cstdint>
#include <cstddef>

#define L_SEQ 2048
#define EMB   1024
#define NB    8
#define MTOT  (NB * L_SEQ)   // 16384
#define NPK   768            // packed channels (heads 0,1,2,5,6,7)

// ---------------- scratch (static device arrays; no allocation) ----------------
__device__ __half g_xt [(size_t)MTOT * EMB];   // fp16, K-permuted x
__device__ __half g_w1 [(size_t)NPK * EMB];    // fp16, K-permuted W_in (768 packed rows)
__device__ __half g_w2 [(size_t)EMB * NPK];    // fp16, K-permuted W_out (768 packed cols)
__device__ __half g_v  [(size_t)MTOT * NPK];   // v = x @ W_in_p^T (fp16, packed 768)
__device__ __half g_z  [(size_t)MTOT * NPK];   // band-mixed v (fp16, K-permuted, 768)
__device__ float  g_xw [(size_t)NB * 2 * EMB]; // weighted x rows for heads 3,4
__device__ float  g_zc [(size_t)NB * 256];     // constant attended rows, heads 3,4
__device__ float  g_bias[(size_t)NB * EMB];    // per-batch output bias from heads 3,4

// Head 3/4 original channels: 384..639.  packed(cp) -> orig: cp<384 ? cp : cp+256.

// K-permutation on k-pairs q within each 64-element K block (qq = q & 31):
//   pp(qq) = (qq&3)*8 + (qq>>4)*4 + ((qq>>2)&3)
__device__ __forceinline__ int ppmap(int qq) {
    return ((qq & 3) << 3) + ((qq >> 4) << 2) + ((qq >> 2) & 3);
}

// ---------------- fp32 -> fp16 conversion + K-permute (x: rows of 1024) -------
__global__ void cvt_perm_h(const float* __restrict__ in, __half* __restrict__ out, int n4) {
    int i = blockIdx.x * blockDim.x + threadIdx.x;
    if (i < n4) {
        float4 v = ((const float4*)in)[i];
        int k  = i * 4;
        int kb = k & ~63;
        int qq = (k >> 1) & 31;
        int pp = ppmap(qq);
        __half2* o = (__half2*)out;
        o[(kb >> 1) + pp]     = __floats2half2_rn(v.x, v.y);
        o[(kb >> 1) + pp + 8] = __floats2half2_rn(v.z, v.w);
    }
}

// W_in packed: out row cp (768 rows of K=1024, K-permuted), src row orig(cp)
__global__ void cvt_w1p(const float* __restrict__ in, __half* __restrict__ out, int n4) {
    int i = blockIdx.x * blockDim.x + threadIdx.x;
    if (i < n4) {                                  // n4 = 768*1024/4
        int k4  = i * 4;
        int row = k4 >> 10;
        int k   = k4 & 1023;
        int srow = row < 384 ? row : row + 256;
        float4 v = *(const float4*)(in + (size_t)srow * 1024 + k);
        int kb = k & ~63;
        int qq = (k >> 1) & 31;
        int pp = ppmap(qq);
        __half2* o = (__half2*)(out + (size_t)row * 1024);
        o[(kb >> 1) + pp]     = __floats2half2_rn(v.x, v.y);
        o[(kb >> 1) + pp + 8] = __floats2half2_rn(v.z, v.w);
    }
}

// W_out packed: out rows n (1024 rows of K=768 packed cols, K-permuted)
__global__ void cvt_w2p(const float* __restrict__ in, __half* __restrict__ out, int n4) {
    int i = blockIdx.x * blockDim.x + threadIdx.x;
    if (i < n4) {                                  // n4 = 1024*768/4
        int k4 = i * 4;
        int n  = k4 / NPK;
        int kk = k4 - n * NPK;                     // packed col, multiple of 4
        int sc = kk < 384 ? kk : kk + 256;
        float4 v = *(const float4*)(in + (size_t)n * 1024 + sc);
        int kb = kk & ~63;
        int qq = (kk >> 1) & 31;
        int pp = ppmap(qq);
        __half2* o = (__half2*)(out + (size_t)n * NPK);
        o[(kb >> 1) + pp]     = __floats2half2_rn(v.x, v.y);
        o[(kb >> 1) + pp + 8] = __floats2half2_rn(v.z, v.w);
    }
}

// ---------------- common GEMM pieces (proven schedule) ----------------
#define BM 128
#define BN 128
#define BK 64
#define NSTG 4
#define STG_B ((BM + BN) * BK * 2)   // 32768 bytes
#define GSMEM (NSTG * STG_B)         // 131072

__device__ __forceinline__ void cp16(uint32_t saddr, const void* g) {
    asm volatile("cp.async.cg.shared.global [%0], [%1], 16;\n" :: "r"(saddr), "l"(g));
}
__device__ __forceinline__ void mma16(float* d, uint32_t a0, uint32_t a1, uint32_t a2,
                                      uint32_t a3, uint32_t b0, uint32_t b1) {
    asm volatile(
        "mma.sync.aligned.m16n8k16.row.col.f32.f16.f16.f32 "
        "{%0,%1,%2,%3}, {%4,%5,%6,%7}, {%8,%9}, {%0,%1,%2,%3};\n"
        : "+f"(d[0]), "+f"(d[1]), "+f"(d[2]), "+f"(d[3])
        : "r"(a0), "r"(a1), "r"(a2), "r"(a3), "r"(b0), "r"(b1));
}

// =====================================================================
// GEMM1 (standalone): v[M,NPK](fp16) = xt[M,1024] @ w1[NPK,1024]^T
// Proven BM=BN=128/BK=64 schedule, 512 threads, warp tile 32x32,
// half-kt fragment double buffering.  Only the epilogue differs (fp16).
// =====================================================================
__global__ void __launch_bounds__(512, 1) gemm1_h(
    const __half* __restrict__ A, const __half* __restrict__ B, __half* __restrict__ C)
{
    constexpr int K = 1024;
    constexpr int NKT = K / BK;
    extern __shared__ char smc[];
    const int tid  = threadIdx.x;
    const int warp = tid >> 5, lane = tid & 31;
    const int wm = warp >> 2, wn = warp & 3;
    const int g  = lane >> 2, tg = lane & 3;
    const int m0 = blockIdx.y * BM;
    const int n0 = blockIdx.x * BN;

    float acc[2][4][4];
    #pragma unroll
    for (int a = 0; a < 2; a++)
        #pragma unroll
        for (int b = 0; b < 4; b++)
            #pragma unroll
            for (int c = 0; c < 4; c++) acc[a][b][c] = 0.f;

    const int lr  = tid >> 3;
    const int lcc = tid & 7;
    const __half* Ag = A + (size_t)(m0 + lr) * K + lcc * 8;
    const __half* Bg = B + (size_t)(n0 + lr) * K + lcc * 8;
    const uint32_t smb   = (uint32_t)__cvta_generic_to_shared(smc);
    const uint32_t stoff = (uint32_t)(lr * 128 + ((lcc ^ (lr & 7)) << 4));

    auto loadst = [&](int s) {
        uint32_t sa = smb + (uint32_t)s * STG_B + stoff;
        uint32_t sb = sa + (uint32_t)(BM * BK * 2);
        cp16(sa,              Ag);
        cp16(sa + 64u * 128u, Ag + (size_t)64 * K);
        cp16(sb,              Bg);
        cp16(sb + 64u * 128u, Bg + (size_t)64 * K);
        Ag += BK; Bg += BK;
        asm volatile("cp.async.commit_group;\n" ::: "memory");
    };

    const uint32_t c0 = (uint32_t)(((2 * tg)     ^ g) << 4);
    const uint32_t c1 = (uint32_t)(((2 * tg + 1) ^ g) << 4);

    float4 af0[2][2], bf0[4], af1[2][2], bf1[4];

    auto loadfrag = [&](float4 (&af)[2][2], float4 (&bf)[4], const char* stg, uint32_t co) {
        #pragma unroll
        for (int mt = 0; mt < 2; mt++)
            #pragma unroll
            for (int rh = 0; rh < 2; rh++)
                af[mt][rh] = *(const float4*)(stg + (wm * 32 + mt * 16 + rh * 8 + g) * 128 + co);
        #pragma unroll
        for (int nt = 0; nt < 4; nt++)
            bf[nt] = *(const float4*)(stg + BM * BK * 2 + (wn * 32 + nt * 8 + g) * 128 + co);
    };

    auto mma_half = [&](const float4 (&af)[2][2], const float4 (&bf)[4]) {
        #pragma unroll
        for (int e = 0; e < 2; e++) {
            #pragma unroll
            for (int mt = 0; mt < 2; mt++) {
                uint32_t a0 = __float_as_uint(((const float*)&af[mt][0])[2 * e]);
                uint32_t a1 = __float_as_uint(((const float*)&af[mt][1])[2 * e]);
                uint32_t a2 = __float_as_uint(((const float*)&af[mt][0])[2 * e + 1]);
                uint32_t a3 = __float_as_uint(((const float*)&af[mt][1])[2 * e + 1]);
                #pragma unroll
                for (int nt = 0; nt < 4; nt++) {
                    uint32_t b0 = __float_as_uint(((const float*)&bf[nt])[2 * e]);
                    uint32_t b1 = __float_as_uint(((const float*)&bf[nt])[2 * e + 1]);
                    mma16(acc[mt][nt], a0, a1, a2, a3, b0, b1);
                }
            }
        }
    };

    loadst(0); loadst(1); loadst(2);
    asm volatile("cp.async.wait_group 2;\n" ::: "memory");
    __syncthreads();
    loadfrag(af0, bf0, smc, c0);

    #pragma unroll 1
    for (int kt = 0; kt < NKT; kt++) {
        const char* stgk = smc + (size_t)(kt & 3) * STG_B;
        loadfrag(af1, bf1, stgk, c1);
        mma_half(af0, bf0);
        if (kt < NKT - 1) {
            if (kt < NKT - 2) asm volatile("cp.async.wait_group 1;\n" ::: "memory");
            else              asm volatile("cp.async.wait_group 0;\n" ::: "memory");
            __syncthreads();
            if (kt < NKT - 3) loadst((kt + 3) & 3);
            const char* stgn = smc + (size_t)((kt + 1) & 3) * STG_B;
            loadfrag(af0, bf0, stgn, c0);
        }
        mma_half(af1, bf1);
    }

    // ---- epilogue: fp16 stores ----
    #pragma unroll
    for (int mt = 0; mt < 2; mt++) {
        #pragma unroll
        for (int nt = 0; nt < 4; nt++) {
            int row = m0 + wm * 32 + mt * 16 + g;
            int col = n0 + wn * 32 + nt * 8 + (tg << 1);
            *(__half2*)&C[(size_t)row * NPK + col] =
                __floats2half2_rn(acc[mt][nt][0], acc[mt][nt][1]);
            *(__half2*)&C[(size_t)(row + 8) * NPK + col] =
                __floats2half2_rn(acc[mt][nt][2], acc[mt][nt][3]);
        }
    }
}

// =====================================================================
// GEMM2 (exact R13 template): out[M,1024](fp32,+bias) = z[M,768] @ w2^T
// =====================================================================
template<int K, int NOUT, bool ADD_BIAS>
__global__ void __launch_bounds__(512, 1) gemm_f16_t(
    const __half* __restrict__ A, const __half* __restrict__ B, float* __restrict__ C,
    const float* __restrict__ bias)
{
    constexpr int NKT = K / BK;
    extern __shared__ char smc[];
    const int tid  = threadIdx.x;
    const int warp = tid >> 5, lane = tid & 31;
    const int wm = warp >> 2, wn = warp & 3;
    const int g  = lane >> 2, tg = lane & 3;
    const int m0 = blockIdx.y * BM;
    const int n0 = blockIdx.x * BN;

    float acc[2][4][4];
    #pragma unroll
    for (int a = 0; a < 2; a++)
        #pragma unroll
        for (int b = 0; b < 4; b++)
            #pragma unroll
            for (int c = 0; c < 4; c++) acc[a][b][c] = 0.f;

    const int lr  = tid >> 3;
    const int lcc = tid & 7;
    const __half* Ag = A + (size_t)(m0 + lr) * K + lcc * 8;
    const __half* Bg = B + (size_t)(n0 + lr) * K + lcc * 8;
    const uint32_t smb   = (uint32_t)__cvta_generic_to_shared(smc);
    const uint32_t stoff = (uint32_t)(lr * 128 + ((lcc ^ (lr & 7)) << 4));

    auto loadst = [&](int s) {
        uint32_t sa = smb + (uint32_t)s * STG_B + stoff;
        uint32_t sb = sa + (uint32_t)(BM * BK * 2);
        cp16(sa,              Ag);
        cp16(sa + 64u * 128u, Ag + (size_t)64 * K);
        cp16(sb,              Bg);
        cp16(sb + 64u * 128u, Bg + (size_t)64 * K);
        Ag += BK; Bg += BK;
        asm volatile("cp.async.commit_group;\n" ::: "memory");
    };

    const uint32_t c0 = (uint32_t)(((2 * tg)     ^ g) << 4);
    const uint32_t c1 = (uint32_t)(((2 * tg + 1) ^ g) << 4);

    float4 af0[2][2], bf0[4], af1[2][2], bf1[4];

    auto loadfrag = [&](float4 (&af)[2][2], float4 (&bf)[4], const char* stg, uint32_t co) {
        #pragma unroll
        for (int mt = 0; mt < 2; mt++)
            #pragma unroll
            for (int rh = 0; rh < 2; rh++)
                af[mt][rh] = *(const float4*)(stg + (wm * 32 + mt * 16 + rh * 8 + g) * 128 + co);
        #pragma unroll
        for (int nt = 0; nt < 4; nt++)
            bf[nt] = *(const float4*)(stg + BM * BK * 2 + (wn * 32 + nt * 8 + g) * 128 + co);
    };

    auto mma_half = [&](const float4 (&af)[2][2], const float4 (&bf)[4]) {
        #pragma unroll
        for (int e = 0; e < 2; e++) {
            #pragma unroll
            for (int mt = 0; mt < 2; mt++) {
                uint32_t a0 = __float_as_uint(((const float*)&af[mt][0])[2 * e]);
                uint32_t a1 = __float_as_uint(((const float*)&af[mt][1])[2 * e]);
                uint32_t a2 = __float_as_uint(((const float*)&af[mt][0])[2 * e + 1]);
                uint32_t a3 = __float_as_uint(((const float*)&af[mt][1])[2 * e + 1]);
                #pragma unroll
                for (int nt = 0; nt < 4; nt++) {
                    uint32_t b0 = __float_as_uint(((const float*)&bf[nt])[2 * e]);
                    uint32_t b1 = __float_as_uint(((const float*)&bf[nt])[2 * e + 1]);
                    mma16(acc[mt][nt], a0, a1, a2, a3, b0, b1);
                }
            }
        }
    };

    loadst(0); loadst(1); loadst(2);
    asm volatile("cp.async.wait_group 2;\n" ::: "memory");
    __syncthreads();
    loadfrag(af0, bf0, smc, c0);

    #pragma unroll 1
    for (int kt = 0; kt < NKT; kt++) {
        const char* stgk = smc + (size_t)(kt & 3) * STG_B;
        loadfrag(af1, bf1, stgk, c1);
        mma_half(af0, bf0);
        if (kt < NKT - 1) {
            if (kt < NKT - 2) asm volatile("cp.async.wait_group 1;\n" ::: "memory");
            else              asm volatile("cp.async.wait_group 0;\n" ::: "memory");
            __syncthreads();
            if (kt < NKT - 3) loadst((kt + 3) & 3);
            const char* stgn = smc + (size_t)((kt + 1) & 3) * STG_B;
            loadfrag(af0, bf0, stgn, c0);
        }
        mma_half(af1, bf1);
    }

    const float* brow = nullptr;
    if (ADD_BIAS) brow = bias + ((size_t)(m0 >> 11) * EMB);
    #pragma unroll
    for (int mt = 0; mt < 2; mt++) {
        #pragma unroll
        for (int nt = 0; nt < 4; nt++) {
            int row = m0 + wm * 32 + mt * 16 + g;
            int col = n0 + wn * 32 + nt * 8 + (tg << 1);
            float2 v01 = make_float2(acc[mt][nt][0], acc[mt][nt][1]);
            float2 v23 = make_float2(acc[mt][nt][2], acc[mt][nt][3]);
            if (ADD_BIAS) {
                float2 bv = *(const float2*)&brow[col];
                v01.x += bv.x; v01.y += bv.y;
                v23.x += bv.x; v23.y += bv.y;
            }
            *(float2*)&C[(size_t)row * NOUT + col]       = v01;
            *(float2*)&C[(size_t)(row + 8) * NOUT + col] = v23;
        }
    }
}

// ---------------- Gaussian band weights ----------------
__device__ __constant__ float WTC[15] = {
    2.28973485e-11f, 1.52299797e-08f, 3.72665317e-06f, 3.35462628e-04f,
    1.11089965e-02f, 1.35335283e-01f, 6.06530660e-01f, 1.00000000e+00f,
    6.06530660e-01f, 1.35335283e-01f, 1.11089965e-02f, 3.35462628e-04f,
    3.72665317e-06f, 1.52299797e-08f, 2.28973485e-11f };

// ---------------- banded Gaussian mixing (6 packed heads, fp16 v) ----------
__global__ void __launch_bounds__(128) band_kernel(const __half* __restrict__ v,
                                                   __half* __restrict__ z)
{
    const int p  = threadIdx.x;          // 0..127
    const int q0 = blockIdx.x * 32;
    const int hp = blockIdx.y;           // 0..5
    const int b  = blockIdx.z;

    const __half* vp = v + (size_t)b * L_SEQ * NPK + hp * 128 + p;
    const int c_ = hp * 128 + p;
    const int qq_ = (c_ >> 1) & 31;
    const int pp  = ppmap(qq_);
    const int pc  = (c_ & ~63) + pp * 2 + (c_ & 1);
    __half* zp = z + ((size_t)(b * L_SEQ + q0)) * NPK + pc;

    const int m3 = hp % 3;
    const int sh = (m3 == 0) ? 0 : ((m3 == 1) ? -1 : 1);
    const int cb = q0 + sh;

    float r[15];
    #pragma unroll
    for (int i = 0; i < 15; i++) {
        int j = cb - 7 + i;
        r[i] = (j >= 0 && j < L_SEQ) ? __half2float(vp[(size_t)j * NPK]) : 0.f;
    }

    #pragma unroll
    for (int qq = 0; qq < 32; qq++) {
        const int c = cb + qq;
        float acc = 0.f, Z = 0.f;
        #pragma unroll
        for (int i = 0; i < 15; i++) {
            int j = c - 7 + i;
            if (j >= 0 && j < L_SEQ) { Z += WTC[i]; acc += WTC[i] * r[(i + qq) % 15]; }
        }
        zp[(size_t)qq * NPK] = __float2half_rn(acc / Z);
        int jn = c + 8;
        r[qq % 15] = (jn >= 0 && jn < L_SEQ) ? __half2float(vp[(size_t)jn * NPK]) : 0.f;
    }
}

// ---------------- heads 3/4 constant path (fp32 exact) ----------
// Step 1: xw[b,h,:] = sum_jj (w_jj / Z) * x[b, j(jj), :]
__global__ void __launch_bounds__(256) xw_kernel(const float* __restrict__ x,
                                                 float* __restrict__ xw)
{
    const int b  = blockIdx.x;
    const int e4 = threadIdx.x;          // float4 index 0..255
    float Z = 0.f;
    #pragma unroll
    for (int i = 0; i < 8; i++) Z += WTC[7 + i];
    const float inz = 1.f / Z;

    const float4* xb = (const float4*)(x + (size_t)b * L_SEQ * EMB);
    float4 s0 = make_float4(0.f, 0.f, 0.f, 0.f);
    float4 s1 = make_float4(0.f, 0.f, 0.f, 0.f);
    #pragma unroll
    for (int jj = 0; jj < 8; jj++) {
        float w0 = WTC[7 + jj] * inz;
        float4 a = xb[(size_t)jj * 256 + e4];
        s0.x += w0 * a.x; s0.y += w0 * a.y; s0.z += w0 * a.z; s0.w += w0 * a.w;
        float w1 = WTC[jj] * inz;
        float4 d = xb[(size_t)(L_SEQ - 8 + jj) * 256 + e4];
        s1.x += w1 * d.x; s1.y += w1 * d.y; s1.z += w1 * d.z; s1.w += w1 * d.w;
    }
    ((float4*)(xw + (size_t)b * 2 * EMB))[e4]       = s0;
    ((float4*)(xw + (size_t)b * 2 * EMB + EMB))[e4] = s1;
}

// Step 2: zc[b,c] = xw[b, h(c), :] . W_in[384+c, :]  (h = c>=128)
__global__ void __launch_bounds__(256) zc_kernel(const float* __restrict__ xw,
                                                 const float* __restrict__ Win,
                                                 float* __restrict__ zc)
{
    const int gw   = blockIdx.x * 8 + (threadIdx.x >> 5);  // global warp 0..2047
    const int lane = threadIdx.x & 31;
    const int c = gw & 255;
    const int b = gw >> 8;
    const int h = (c >> 7) & 1;

    const float4* xr = (const float4*)(xw + ((size_t)b * 2 + h) * EMB);
    const float4* wr = (const float4*)(Win + (size_t)(384 + c) * EMB);
    float s = 0.f;
    #pragma unroll
    for (int i = 0; i < 8; i++) {
        float4 a = xr[lane + i * 32];
        float4 w = wr[lane + i * 32];
        s += a.x * w.x + a.y * w.y + a.z * w.z + a.w * w.w;
    }
    #pragma unroll
    for (int o = 16; o > 0; o >>= 1) s += __shfl_down_sync(0xffffffffu, s, o);
    if (lane == 0) zc[(size_t)b * 256 + c] = s;
}

// Step 3: bias[b, n] = sum_c zc[b,c] * W_out[n, 384+c]  -- warp per output
__global__ void __launch_bounds__(256) bias_kernel(const float* __restrict__ zc,
                                                   const float* __restrict__ Wout,
                                                   float* __restrict__ bias)
{
    const int gw   = blockIdx.x * 8 + (threadIdx.x >> 5);  // 0..8191
    const int lane = threadIdx.x & 31;
    const int n = gw & 1023;
    const int b = gw >> 10;

    const float4* zr = (const float4*)(zc + (size_t)b * 256);
    const float4* wr = (const float4*)(Wout + (size_t)n * EMB + 384);
    float s = 0.f;
    #pragma unroll
    for (int i = 0; i < 2; i++) {
        float4 zv = zr[lane + i * 32];
        float4 wv = wr[lane + i * 32];
        s += zv.x * wv.x + zv.y * wv.y + zv.z * wv.z + zv.w * wv.w;
    }
    #pragma unroll
    for (int o = 16; o > 0; o >>= 1) s += __shfl_down_sync(0xffffffffu, s, o);
    if (lane == 0) bias[(size_t)b * EMB + n] = s;
}

// ---------------- launch ----------------
extern "C" void kernel_launch(void* const* d_in, const int* in_sizes, int n_in,
                              void* d_out, int out_size)
{
    const float* x   = (const float*)d_in[0];
    const float* Win = (const float*)d_in[1];
    const float* Wou = (const float*)d_in[2];
    float* out = (float*)d_out;

    __half *xt, *w1, *w2, *v, *z;
    float *xw, *zc, *bias;
    cudaGetSymbolAddress((void**)&xt,  g_xt);
    cudaGetSymbolAddress((void**)&w1,  g_w1);
    cudaGetSymbolAddress((void**)&w2,  g_w2);
    cudaGetSymbolAddress((void**)&v,   g_v);
    cudaGetSymbolAddress((void**)&z,   g_z);
    cudaGetSymbolAddress((void**)&xw,  g_xw);
    cudaGetSymbolAddress((void**)&zc,  g_zc);
    cudaGetSymbolAddress((void**)&bias,g_bias);

    cudaFuncSetAttribute(gemm1_h,
                         cudaFuncAttributeMaxDynamicSharedMemorySize, GSMEM);
    cudaFuncSetAttribute(gemm_f16_t<NPK, 1024, true>,
                         cudaFuncAttributeMaxDynamicSharedMemorySize, GSMEM);

    const int nx4  = (MTOT * EMB) / 4;
    const int nw14 = (NPK * EMB) / 4;
    const int nw24 = (EMB * NPK) / 4;
    cvt_perm_h<<<(nx4  + 255) / 256, 256>>>(x,   xt, nx4);
    cvt_w1p  <<<(nw14 + 255) / 256, 256>>>(Win, w1, nw14);
    cvt_w2p  <<<(nw24 + 255) / 256, 256>>>(Wou, w2, nw24);

    // heads 3/4 constant path (fp32 exact, tiny)
    xw_kernel  <<<NB, 256>>>(x, xw);
    zc_kernel  <<<256, 256>>>(xw, Win, zc);
    bias_kernel<<<1024, 256>>>(zc, Wou, bias);

    // main path (6 packed heads)
    gemm1_h<<<dim3(NPK / BN, MTOT / BM), 512, GSMEM>>>(xt, w1, v);
    band_kernel<<<dim3(L_SEQ / 32, 6, NB), 128>>>(v, z);
    gemm_f16_t<NPK, 1024, true><<<dim3(EMB / BN, MTOT / BM), 512, GSMEM>>>(z, w2, out, bias);
}

// round 15
// speedup vs baseline: 1.2313x; 1.2313x over previous
#include <cuda_runtime.h>
#include <cuda_fp16.h>
#include <cstdint>
#include <cstddef>

#define L_SEQ 2048
#define EMB   1024
#define NB    8
#define MTOT  (NB * L_SEQ)   // 16384
#define NPK   768            // packed channels (heads 0,1,2,5,6,7)

// ---------------- scratch (static device arrays; no allocation) ----------------
__device__ __half g_xt [(size_t)MTOT * EMB];   // fp16, K-permuted x
__device__ __half g_w1 [(size_t)NPK * EMB];    // fp16, K-permuted W_in (768 packed rows)
__device__ __half g_w2 [(size_t)EMB * NPK];    // fp16, K-permuted W_out (768 packed cols)
__device__ float  g_v  [(size_t)MTOT * NPK];   // v = x @ W_in_p^T (fp32, packed 768)
__device__ __half g_z  [(size_t)MTOT * NPK];   // band-mixed v (fp16, K-permuted, 768)
__device__ float  g_bias[(size_t)NB * EMB];    // per-batch output bias from heads 3,4

// Head 3/4 original channels: 384..639.  packed(cp) -> orig: cp<384 ? cp : cp+256.

// K-permutation on k-pairs q within each 64-element K block (qq = q & 31):
//   pp(qq) = (qq&3)*8 + (qq>>4)*4 + ((qq>>2)&3)
__device__ __forceinline__ int ppmap(int qq) {
    return ((qq & 3) << 3) + ((qq >> 4) << 2) + ((qq >> 2) & 3);
}

// ---------------- fp32 -> fp16 conversion + K-permute (x: rows of 1024) -------
__global__ void cvt_perm_h(const float* __restrict__ in, __half* __restrict__ out, int n4) {
    int i = blockIdx.x * blockDim.x + threadIdx.x;
    if (i < n4) {
        float4 v = ((const float4*)in)[i];
        int k  = i * 4;
        int kb = k & ~63;
        int qq = (k >> 1) & 31;
        int pp = ppmap(qq);
        __half2* o = (__half2*)out;
        o[(kb >> 1) + pp]     = __floats2half2_rn(v.x, v.y);
        o[(kb >> 1) + pp + 8] = __floats2half2_rn(v.z, v.w);
    }
}

// W_in packed: out row cp (768 rows of K=1024, K-permuted), src row orig(cp)
__global__ void cvt_w1p(const float* __restrict__ in, __half* __restrict__ out, int n4) {
    int i = blockIdx.x * blockDim.x + threadIdx.x;
    if (i < n4) {                                  // n4 = 768*1024/4
        int k4  = i * 4;
        int row = k4 >> 10;
        int k   = k4 & 1023;
        int srow = row < 384 ? row : row + 256;
        float4 v = *(const float4*)(in + (size_t)srow * 1024 + k);
        int kb = k & ~63;
        int qq = (k >> 1) & 31;
        int pp = ppmap(qq);
        __half2* o = (__half2*)(out + (size_t)row * 1024);
        o[(kb >> 1) + pp]     = __floats2half2_rn(v.x, v.y);
        o[(kb >> 1) + pp + 8] = __floats2half2_rn(v.z, v.w);
    }
}

// W_out packed: out rows n (1024 rows of K=768 packed cols, K-permuted)
__global__ void cvt_w2p(const float* __restrict__ in, __half* __restrict__ out, int n4) {
    int i = blockIdx.x * blockDim.x + threadIdx.x;
    if (i < n4) {                                  // n4 = 1024*768/4
        int k4 = i * 4;
        int n  = k4 / NPK;
        int kk = k4 - n * NPK;                     // packed col, multiple of 4
        int sc = kk < 384 ? kk : kk + 256;
        float4 v = *(const float4*)(in + (size_t)n * 1024 + sc);
        int kb = kk & ~63;
        int qq = (kk >> 1) & 31;
        int pp = ppmap(qq);
        __half2* o = (__half2*)(out + (size_t)n * NPK);
        o[(kb >> 1) + pp]     = __floats2half2_rn(v.x, v.y);
        o[(kb >> 1) + pp + 8] = __floats2half2_rn(v.z, v.w);
    }
}

// =====================================================================
// fp16 mma.sync GEMM (templated K / output-stride / bias):
//   C[M,NOUT-tilespace] = A[M,K] @ B[*,K]^T   (A,B fp16, K-permuted)
// BM=BN=128, BK=64, 4-stage cp.async ring, 512 threads, warp tile 32x32,
// half-kt fragment double buffering.  ADD_BIAS: += bias[b, col] (b = m0>>11).
// =====================================================================

#define BM 128
#define BN 128
#define BK 64
#define NSTG 4
#define STG_B ((BM + BN) * BK * 2)   // 32768 bytes
#define GSMEM (NSTG * STG_B)         // 131072

__device__ __forceinline__ void cp16(uint32_t saddr, const void* g) {
    asm volatile("cp.async.cg.shared.global [%0], [%1], 16;\n" :: "r"(saddr), "l"(g));
}
__device__ __forceinline__ void mma16(float* d, uint32_t a0, uint32_t a1, uint32_t a2,
                                      uint32_t a3, uint32_t b0, uint32_t b1) {
    asm volatile(
        "mma.sync.aligned.m16n8k16.row.col.f32.f16.f16.f32 "
        "{%0,%1,%2,%3}, {%4,%5,%6,%7}, {%8,%9}, {%0,%1,%2,%3};\n"
        : "+f"(d[0]), "+f"(d[1]), "+f"(d[2]), "+f"(d[3])
        : "r"(a0), "r"(a1), "r"(a2), "r"(a3), "r"(b0), "r"(b1));
}

template<int K, int NOUT, bool ADD_BIAS>
__global__ void __launch_bounds__(512, 1) gemm_f16_t(
    const __half* __restrict__ A, const __half* __restrict__ B, float* __restrict__ C,
    const float* __restrict__ bias)
{
    constexpr int NKT = K / BK;
    extern __shared__ char smc[];
    const int tid  = threadIdx.x;
    const int warp = tid >> 5, lane = tid & 31;
    const int wm = warp >> 2, wn = warp & 3;   // 4 (m) x 4 (n), warp tile 32x32
    const int g  = lane >> 2, tg = lane & 3;
    const int m0 = blockIdx.y * BM;
    const int n0 = blockIdx.x * BN;

    float acc[2][4][4];
    #pragma unroll
    for (int a = 0; a < 2; a++)
        #pragma unroll
        for (int b = 0; b < 4; b++)
            #pragma unroll
            for (int c = 0; c < 4; c++) acc[a][b][c] = 0.f;

    // ---- loader: 4 cp.async of 16B per thread per stage ----
    const int lr  = tid >> 3;        // 0..63
    const int lcc = tid & 7;         // chunk 0..7
    const __half* Ag = A + (size_t)(m0 + lr) * K + lcc * 8;
    const __half* Bg = B + (size_t)(n0 + lr) * K + lcc * 8;
    const uint32_t smb   = (uint32_t)__cvta_generic_to_shared(smc);
    const uint32_t stoff = (uint32_t)(lr * 128 + ((lcc ^ (lr & 7)) << 4));

    auto loadst = [&](int s) {
        uint32_t sa = smb + (uint32_t)s * STG_B + stoff;
        uint32_t sb = sa + (uint32_t)(BM * BK * 2);
        cp16(sa,              Ag);
        cp16(sa + 64u * 128u, Ag + (size_t)64 * K);
        cp16(sb,              Bg);
        cp16(sb + 64u * 128u, Bg + (size_t)64 * K);
        Ag += BK; Bg += BK;
        asm volatile("cp.async.commit_group;\n" ::: "memory");
    };

    const uint32_t c0 = (uint32_t)(((2 * tg)     ^ g) << 4);
    const uint32_t c1 = (uint32_t)(((2 * tg + 1) ^ g) << 4);

    float4 af0[2][2], bf0[4], af1[2][2], bf1[4];

    auto loadfrag = [&](float4 (&af)[2][2], float4 (&bf)[4], const char* stg, uint32_t co) {
        #pragma unroll
        for (int mt = 0; mt < 2; mt++)
            #pragma unroll
            for (int rh = 0; rh < 2; rh++)
                af[mt][rh] = *(const float4*)(stg + (wm * 32 + mt * 16 + rh * 8 + g) * 128 + co);
        #pragma unroll
        for (int nt = 0; nt < 4; nt++)
            bf[nt] = *(const float4*)(stg + BM * BK * 2 + (wn * 32 + nt * 8 + g) * 128 + co);
    };

    auto mma_half = [&](const float4 (&af)[2][2], const float4 (&bf)[4]) {
        #pragma unroll
        for (int e = 0; e < 2; e++) {
            #pragma unroll
            for (int mt = 0; mt < 2; mt++) {
                uint32_t a0 = __float_as_uint(((const float*)&af[mt][0])[2 * e]);
                uint32_t a1 = __float_as_uint(((const float*)&af[mt][1])[2 * e]);
                uint32_t a2 = __float_as_uint(((const float*)&af[mt][0])[2 * e + 1]);
                uint32_t a3 = __float_as_uint(((const float*)&af[mt][1])[2 * e + 1]);
                #pragma unroll
                for (int nt = 0; nt < 4; nt++) {
                    uint32_t b0 = __float_as_uint(((const float*)&bf[nt])[2 * e]);
                    uint32_t b1 = __float_as_uint(((const float*)&bf[nt])[2 * e + 1]);
                    mma16(acc[mt][nt], a0, a1, a2, a3, b0, b1);
                }
            }
        }
    };

    // ---- prologue ----
    loadst(0); loadst(1); loadst(2);
    asm volatile("cp.async.wait_group 2;\n" ::: "memory");
    __syncthreads();
    loadfrag(af0, bf0, smc, c0);

    // ---- mainloop ----
    #pragma unroll 1
    for (int kt = 0; kt < NKT; kt++) {
        const char* stgk = smc + (size_t)(kt & 3) * STG_B;
        loadfrag(af1, bf1, stgk, c1);
        mma_half(af0, bf0);

        if (kt < NKT - 1) {
            if (kt < NKT - 2) asm volatile("cp.async.wait_group 1;\n" ::: "memory");
            else              asm volatile("cp.async.wait_group 0;\n" ::: "memory");
            __syncthreads();
            if (kt < NKT - 3) loadst((kt + 3) & 3);
            const char* stgn = smc + (size_t)((kt + 1) & 3) * STG_B;
            loadfrag(af0, bf0, stgn, c0);
        }
        mma_half(af1, bf1);
    }

    // ---- epilogue ----
    const float* brow = nullptr;
    if (ADD_BIAS) brow = bias + ((size_t)(m0 >> 11) * EMB);
    #pragma unroll
    for (int mt = 0; mt < 2; mt++) {
        #pragma unroll
        for (int nt = 0; nt < 4; nt++) {
            int row = m0 + wm * 32 + mt * 16 + g;
            int col = n0 + wn * 32 + nt * 8 + (tg << 1);
            float2 v01 = make_float2(acc[mt][nt][0], acc[mt][nt][1]);
            float2 v23 = make_float2(acc[mt][nt][2], acc[mt][nt][3]);
            if (ADD_BIAS) {
                float2 bv = *(const float2*)&brow[col];
                v01.x += bv.x; v01.y += bv.y;
                v23.x += bv.x; v23.y += bv.y;
            }
            *(float2*)&C[(size_t)row * NOUT + col]       = v01;
            *(float2*)&C[(size_t)(row + 8) * NOUT + col] = v23;
        }
    }
}

// ---------------- Gaussian band weights ----------------
__device__ __constant__ float WTC[15] = {
    2.28973485e-11f, 1.52299797e-08f, 3.72665317e-06f, 3.35462628e-04f,
    1.11089965e-02f, 1.35335283e-01f, 6.06530660e-01f, 1.00000000e+00f,
    6.06530660e-01f, 1.35335283e-01f, 1.11089965e-02f, 3.35462628e-04f,
    3.72665317e-06f, 1.52299797e-08f, 2.28973485e-11f };

// ---------------- banded Gaussian mixing (6 packed heads, fp32 v) ----------
__global__ void __launch_bounds__(128) band_kernel(const float* __restrict__ v,
                                                   __half* __restrict__ z)
{
    const int p  = threadIdx.x;          // 0..127
    const int q0 = blockIdx.x * 32;
    const int hp = blockIdx.y;           // 0..5
    const int b  = blockIdx.z;

    const float* vp = v + (size_t)b * L_SEQ * NPK + hp * 128 + p;
    const int c_ = hp * 128 + p;
    const int qq_ = (c_ >> 1) & 31;
    const int pp  = ppmap(qq_);
    const int pc  = (c_ & ~63) + pp * 2 + (c_ & 1);
    __half* zp = z + ((size_t)(b * L_SEQ + q0)) * NPK + pc;

    const int m3 = hp % 3;
    const int sh = (m3 == 0) ? 0 : ((m3 == 1) ? -1 : 1);
    const int cb = q0 + sh;

    float r[15];
    #pragma unroll
    for (int i = 0; i < 15; i++) {
        int j = cb - 7 + i;
        r[i] = (j >= 0 && j < L_SEQ) ? vp[(size_t)j * NPK] : 0.f;
    }

    #pragma unroll
    for (int qq = 0; qq < 32; qq++) {
        const int c = cb + qq;
        float acc = 0.f, Z = 0.f;
        #pragma unroll
        for (int i = 0; i < 15; i++) {
            int j = c - 7 + i;
            if (j >= 0 && j < L_SEQ) { Z += WTC[i]; acc += WTC[i] * r[(i + qq) % 15]; }
        }
        zp[(size_t)qq * NPK] = __float2half_rn(acc / Z);
        int jn = c + 8;
        r[qq % 15] = (jn >= 0 && jn < L_SEQ) ? vp[(size_t)jn * NPK] : 0.f;
    }
}

// ---------------- heads 3/4 constant path: single fused kernel -------------
// grid (4, NB), 256 threads.  b = blockIdx.y, nchunk = blockIdx.x.
// Phase 1: xw[2][EMB] in smem (weighted edge rows of x; redundant per nchunk).
// Phase 2: zc[256] in smem (warp-per-output dot with W_in rows 384..639).
// Phase 3: bias[b, nchunk*256 .. +255] (warp-per-output dot with zc).
// All fp32, summation order identical to the previous 3-kernel chain.
__global__ void __launch_bounds__(256) head34_kernel(const float* __restrict__ x,
                                                     const float* __restrict__ Win,
                                                     const float* __restrict__ Wout,
                                                     float* __restrict__ bias)
{
    __shared__ float xs[2 * EMB];
    __shared__ float zcs[256];
    const int b  = blockIdx.y;
    const int nc = blockIdx.x;
    const int t  = threadIdx.x;
    const int w  = t >> 5, lane = t & 31;

    // ---- phase 1: weighted x rows ----
    float Z = 0.f;
    #pragma unroll
    for (int i = 0; i < 8; i++) Z += WTC[7 + i];
    const float inz = 1.f / Z;

    {
        const float4* xb = (const float4*)(x + (size_t)b * L_SEQ * EMB);
        float4 s0 = make_float4(0.f, 0.f, 0.f, 0.f);
        float4 s1 = make_float4(0.f, 0.f, 0.f, 0.f);
        #pragma unroll
        for (int jj = 0; jj < 8; jj++) {
            float w0 = WTC[7 + jj] * inz;
            float4 a = xb[(size_t)jj * 256 + t];
            s0.x += w0 * a.x; s0.y += w0 * a.y; s0.z += w0 * a.z; s0.w += w0 * a.w;
            float w1 = WTC[jj] * inz;
            float4 d = xb[(size_t)(L_SEQ - 8 + jj) * 256 + t];
            s1.x += w1 * d.x; s1.y += w1 * d.y; s1.z += w1 * d.z; s1.w += w1 * d.w;
        }
        ((float4*)xs)[t]       = s0;
        ((float4*)xs)[t + 256] = s1;
    }
    __syncthreads();

    // ---- phase 2: zc[c] = xs[h(c)] . Win[384+c] ----
    #pragma unroll 1
    for (int oi = 0; oi < 32; oi++) {
        const int c = w * 32 + oi;
        const int h = (c >> 7) & 1;
        const float4* xr = (const float4*)(xs + h * EMB);
        const float4* wr = (const float4*)(Win + (size_t)(384 + c) * EMB);
        float s = 0.f;
        #pragma unroll
        for (int i = 0; i < 8; i++) {
            float4 a  = xr[lane + i * 32];
            float4 ww = wr[lane + i * 32];
            s += a.x * ww.x + a.y * ww.y + a.z * ww.z + a.w * ww.w;
        }
        #pragma unroll
        for (int o = 16; o > 0; o >>= 1) s += __shfl_down_sync(0xffffffffu, s, o);
        if (lane == 0) zcs[c] = s;
    }
    __syncthreads();

    // ---- phase 3: bias for this block's 256 n values ----
    #pragma unroll 1
    for (int oi = 0; oi < 32; oi++) {
        const int n = nc * 256 + w * 32 + oi;
        const float4* zr = (const float4*)zcs;
        const float4* wr = (const float4*)(Wout + (size_t)n * EMB + 384);
        float s = 0.f;
        #pragma unroll
        for (int i = 0; i < 2; i++) {
            float4 zv = zr[lane + i * 32];
            float4 wv = wr[lane + i * 32];
            s += zv.x * wv.x + zv.y * wv.y + zv.z * wv.z + zv.w * wv.w;
        }
        #pragma unroll
        for (int o = 16; o > 0; o >>= 1) s += __shfl_down_sync(0xffffffffu, s, o);
        if (lane == 0) bias[(size_t)b * EMB + n] = s;
    }
}

// ---------------- launch ----------------
extern "C" void kernel_launch(void* const* d_in, const int* in_sizes, int n_in,
                              void* d_out, int out_size)
{
    const float* x   = (const float*)d_in[0];
    const float* Win = (const float*)d_in[1];
    const float* Wou = (const float*)d_in[2];
    float* out = (float*)d_out;

    __half *xt, *w1, *w2, *z;
    float *v, *bias;
    cudaGetSymbolAddress((void**)&xt,  g_xt);
    cudaGetSymbolAddress((void**)&w1,  g_w1);
    cudaGetSymbolAddress((void**)&w2,  g_w2);
    cudaGetSymbolAddress((void**)&v,   g_v);
    cudaGetSymbolAddress((void**)&z,   g_z);
    cudaGetSymbolAddress((void**)&bias,g_bias);

    cudaFuncSetAttribute(gemm_f16_t<1024, NPK, false>,
                         cudaFuncAttributeMaxDynamicSharedMemorySize, GSMEM);
    cudaFuncSetAttribute(gemm_f16_t<NPK, 1024, true>,
                         cudaFuncAttributeMaxDynamicSharedMemorySize, GSMEM);

    const int nx4  = (MTOT * EMB) / 4;
    const int nw14 = (NPK * EMB) / 4;
    const int nw24 = (EMB * NPK) / 4;
    cvt_perm_h<<<(nx4  + 255) / 256, 256>>>(x,   xt, nx4);
    cvt_w1p  <<<(nw14 + 255) / 256, 256>>>(Win, w1, nw14);
    cvt_w2p  <<<(nw24 + 255) / 256, 256>>>(Wou, w2, nw24);

    // heads 3/4 constant path (fp32 exact, single fused kernel)
    head34_kernel<<<dim3(4, NB), 256>>>(x, Win, Wou, bias);

    // main path (6 packed heads)
    gemm_f16_t<1024, NPK, false><<<dim3(NPK / BN, MTOT / BM), 512, GSMEM>>>(xt, w1, v, nullptr);
    band_kernel<<<dim3(L_SEQ / 32, 6, NB), 128>>>(v, z);
    gemm_f16_t<NPK, 1024, true><<<dim3(EMB / BN, MTOT / BM), 512, GSMEM>>>(z, w2, out, bias);
}

// round 16
// speedup vs baseline: 1.4700x; 1.1938x over previous
#include <cuda_runtime.h>
#include <cuda_fp16.h>
#include <cstdint>
#include <cstddef>

#define L_SEQ 2048
#define EMB   1024
#define NB    8
#define MTOT  (NB * L_SEQ)   // 16384
#define NPK   768            // packed channels (heads 0,1,2,5,6,7)

// ---------------- scratch (static device arrays; no allocation) ----------------
__device__ __half g_xt [(size_t)MTOT * EMB];   // fp16, K-permuted x
__device__ __half g_w1 [(size_t)NPK * EMB];    // fp16, K-permuted W_in (768 packed rows)
__device__ __half g_w2 [(size_t)EMB * NPK];    // fp16, K-permuted W_out (768 packed cols)
__device__ float  g_v  [(size_t)MTOT * NPK];   // v = x @ W_in_p^T (fp32, packed 768)
__device__ __half g_z  [(size_t)MTOT * NPK];   // band-mixed v (fp16, K-permuted, 768)
__device__ float  g_xw [(size_t)NB * 2 * EMB]; // weighted x rows for heads 3,4
__device__ float  g_zc [(size_t)NB * 256];     // constant attended rows, heads 3,4
__device__ float  g_bias[(size_t)NB * EMB];    // per-batch output bias from heads 3,4

// Head 3/4 original channels: 384..639.  packed(cp) -> orig: cp<384 ? cp : cp+256.

// K-permutation on k-pairs q within each 64-element K block (qq = q & 31):
//   pp(qq) = (qq&3)*8 + (qq>>4)*4 + ((qq>>2)&3)
__device__ __forceinline__ int ppmap(int qq) {
    return ((qq & 3) << 3) + ((qq >> 4) << 2) + ((qq >> 2) & 3);
}

// ---------------- fp32 -> fp16 conversion + K-permute (x: rows of 1024) -------
__global__ void cvt_perm_h(const float* __restrict__ in, __half* __restrict__ out, int n4) {
    int i = blockIdx.x * blockDim.x + threadIdx.x;
    if (i < n4) {
        float4 v = ((const float4*)in)[i];
        int k  = i * 4;
        int kb = k & ~63;
        int qq = (k >> 1) & 31;
        int pp = ppmap(qq);
        __half2* o = (__half2*)out;
        o[(kb >> 1) + pp]     = __floats2half2_rn(v.x, v.y);
        o[(kb >> 1) + pp + 8] = __floats2half2_rn(v.z, v.w);
    }
}

// W_in packed: out row cp (768 rows of K=1024, K-permuted), src row orig(cp)
__global__ void cvt_w1p(const float* __restrict__ in, __half* __restrict__ out, int n4) {
    int i = blockIdx.x * blockDim.x + threadIdx.x;
    if (i < n4) {                                  // n4 = 768*1024/4
        int k4  = i * 4;
        int row = k4 >> 10;
        int k   = k4 & 1023;
        int srow = row < 384 ? row : row + 256;
        float4 v = *(const float4*)(in + (size_t)srow * 1024 + k);
        int kb = k & ~63;
        int qq = (k >> 1) & 31;
        int pp = ppmap(qq);
        __half2* o = (__half2*)(out + (size_t)row * 1024);
        o[(kb >> 1) + pp]     = __floats2half2_rn(v.x, v.y);
        o[(kb >> 1) + pp + 8] = __floats2half2_rn(v.z, v.w);
    }
}

// W_out packed: out rows n (1024 rows of K=768 packed cols, K-permuted)
__global__ void cvt_w2p(const float* __restrict__ in, __half* __restrict__ out, int n4) {
    int i = blockIdx.x * blockDim.x + threadIdx.x;
    if (i < n4) {                                  // n4 = 1024*768/4
        int k4 = i * 4;
        int n  = k4 / NPK;
        int kk = k4 - n * NPK;                     // packed col, multiple of 4
        int sc = kk < 384 ? kk : kk + 256;
        float4 v = *(const float4*)(in + (size_t)n * 1024 + sc);
        int kb = kk & ~63;
        int qq = (kk >> 1) & 31;
        int pp = ppmap(qq);
        __half2* o = (__half2*)(out + (size_t)n * NPK);
        o[(kb >> 1) + pp]     = __floats2half2_rn(v.x, v.y);
        o[(kb >> 1) + pp + 8] = __floats2half2_rn(v.z, v.w);
    }
}

// =====================================================================
// fp16 mma.sync GEMM (templated K / output-stride / bias):
//   C[M,NOUT-tilespace] = A[M,K] @ B[*,K]^T   (A,B fp16, K-permuted)
// BM=BN=128, BK=64, 4-stage cp.async ring, 512 threads, warp tile 32x32,
// half-kt fragment double buffering.  ADD_BIAS: += bias[b, col] (b = m0>>11).
// =====================================================================

#define BM 128
#define BN 128
#define BK 64
#define NSTG 4
#define STG_B ((BM + BN) * BK * 2)   // 32768 bytes
#define GSMEM (NSTG * STG_B)         // 131072

__device__ __forceinline__ void cp16(uint32_t saddr, const void* g) {
    asm volatile("cp.async.cg.shared.global [%0], [%1], 16;\n" :: "r"(saddr), "l"(g));
}
__device__ __forceinline__ void mma16(float* d, uint32_t a0, uint32_t a1, uint32_t a2,
                                      uint32_t a3, uint32_t b0, uint32_t b1) {
    asm volatile(
        "mma.sync.aligned.m16n8k16.row.col.f32.f16.f16.f32 "
        "{%0,%1,%2,%3}, {%4,%5,%6,%7}, {%8,%9}, {%0,%1,%2,%3};\n"
        : "+f"(d[0]), "+f"(d[1]), "+f"(d[2]), "+f"(d[3])
        : "r"(a0), "r"(a1), "r"(a2), "r"(a3), "r"(b0), "r"(b1));
}

template<int K, int NOUT, bool ADD_BIAS>
__global__ void __launch_bounds__(512, 1) gemm_f16_t(
    const __half* __restrict__ A, const __half* __restrict__ B, float* __restrict__ C,
    const float* __restrict__ bias)
{
    constexpr int NKT = K / BK;
    extern __shared__ char smc[];
    const int tid  = threadIdx.x;
    const int warp = tid >> 5, lane = tid & 31;
    const int wm = warp >> 2, wn = warp & 3;   // 4 (m) x 4 (n), warp tile 32x32
    const int g  = lane >> 2, tg = lane & 3;
    const int m0 = blockIdx.y * BM;
    const int n0 = blockIdx.x * BN;

    float acc[2][4][4];
    #pragma unroll
    for (int a = 0; a < 2; a++)
        #pragma unroll
        for (int b = 0; b < 4; b++)
            #pragma unroll
            for (int c = 0; c < 4; c++) acc[a][b][c] = 0.f;

    // ---- loader: 4 cp.async of 16B per thread per stage ----
    const int lr  = tid >> 3;        // 0..63
    const int lcc = tid & 7;         // chunk 0..7
    const __half* Ag = A + (size_t)(m0 + lr) * K + lcc * 8;
    const __half* Bg = B + (size_t)(n0 + lr) * K + lcc * 8;
    const uint32_t smb   = (uint32_t)__cvta_generic_to_shared(smc);
    const uint32_t stoff = (uint32_t)(lr * 128 + ((lcc ^ (lr & 7)) << 4));

    auto loadst = [&](int s) {
        uint32_t sa = smb + (uint32_t)s * STG_B + stoff;
        uint32_t sb = sa + (uint32_t)(BM * BK * 2);
        cp16(sa,              Ag);
        cp16(sa + 64u * 128u, Ag + (size_t)64 * K);
        cp16(sb,              Bg);
        cp16(sb + 64u * 128u, Bg + (size_t)64 * K);
        Ag += BK; Bg += BK;
        asm volatile("cp.async.commit_group;\n" ::: "memory");
    };

    const uint32_t c0 = (uint32_t)(((2 * tg)     ^ g) << 4);
    const uint32_t c1 = (uint32_t)(((2 * tg + 1) ^ g) << 4);

    float4 af0[2][2], bf0[4], af1[2][2], bf1[4];

    auto loadfrag = [&](float4 (&af)[2][2], float4 (&bf)[4], const char* stg, uint32_t co) {
        #pragma unroll
        for (int mt = 0; mt < 2; mt++)
            #pragma unroll
            for (int rh = 0; rh < 2; rh++)
                af[mt][rh] = *(const float4*)(stg + (wm * 32 + mt * 16 + rh * 8 + g) * 128 + co);
        #pragma unroll
        for (int nt = 0; nt < 4; nt++)
            bf[nt] = *(const float4*)(stg + BM * BK * 2 + (wn * 32 + nt * 8 + g) * 128 + co);
    };

    auto mma_half = [&](const float4 (&af)[2][2], const float4 (&bf)[4]) {
        #pragma unroll
        for (int e = 0; e < 2; e++) {
            #pragma unroll
            for (int mt = 0; mt < 2; mt++) {
                uint32_t a0 = __float_as_uint(((const float*)&af[mt][0])[2 * e]);
                uint32_t a1 = __float_as_uint(((const float*)&af[mt][1])[2 * e]);
                uint32_t a2 = __float_as_uint(((const float*)&af[mt][0])[2 * e + 1]);
                uint32_t a3 = __float_as_uint(((const float*)&af[mt][1])[2 * e + 1]);
                #pragma unroll
                for (int nt = 0; nt < 4; nt++) {
                    uint32_t b0 = __float_as_uint(((const float*)&bf[nt])[2 * e]);
                    uint32_t b1 = __float_as_uint(((const float*)&bf[nt])[2 * e + 1]);
                    mma16(acc[mt][nt], a0, a1, a2, a3, b0, b1);
                }
            }
        }
    };

    // ---- prologue ----
    loadst(0); loadst(1); loadst(2);
    asm volatile("cp.async.wait_group 2;\n" ::: "memory");
    __syncthreads();
    loadfrag(af0, bf0, smc, c0);

    // ---- mainloop ----
    #pragma unroll 1
    for (int kt = 0; kt < NKT; kt++) {
        const char* stgk = smc + (size_t)(kt & 3) * STG_B;
        loadfrag(af1, bf1, stgk, c1);
        mma_half(af0, bf0);

        if (kt < NKT - 1) {
            if (kt < NKT - 2) asm volatile("cp.async.wait_group 1;\n" ::: "memory");
            else              asm volatile("cp.async.wait_group 0;\n" ::: "memory");
            __syncthreads();
            if (kt < NKT - 3) loadst((kt + 3) & 3);
            const char* stgn = smc + (size_t)((kt + 1) & 3) * STG_B;
            loadfrag(af0, bf0, stgn, c0);
        }
        mma_half(af1, bf1);
    }

    // ---- epilogue ----
    const float* brow = nullptr;
    if (ADD_BIAS) brow = bias + ((size_t)(m0 >> 11) * EMB);
    #pragma unroll
    for (int mt = 0; mt < 2; mt++) {
        #pragma unroll
        for (int nt = 0; nt < 4; nt++) {
            int row = m0 + wm * 32 + mt * 16 + g;
            int col = n0 + wn * 32 + nt * 8 + (tg << 1);
            float2 v01 = make_float2(acc[mt][nt][0], acc[mt][nt][1]);
            float2 v23 = make_float2(acc[mt][nt][2], acc[mt][nt][3]);
            if (ADD_BIAS) {
                float2 bv = *(const float2*)&brow[col];
                v01.x += bv.x; v01.y += bv.y;
                v23.x += bv.x; v23.y += bv.y;
            }
            *(float2*)&C[(size_t)row * NOUT + col]       = v01;
            *(float2*)&C[(size_t)(row + 8) * NOUT + col] = v23;
        }
    }
}

// ---------------- Gaussian band weights ----------------
__device__ __constant__ float WTC[15] = {
    2.28973485e-11f, 1.52299797e-08f, 3.72665317e-06f, 3.35462628e-04f,
    1.11089965e-02f, 1.35335283e-01f, 6.06530660e-01f, 1.00000000e+00f,
    6.06530660e-01f, 1.35335283e-01f, 1.11089965e-02f, 3.35462628e-04f,
    3.72665317e-06f, 1.52299797e-08f, 2.28973485e-11f };

// ---------------- banded Gaussian mixing (6 packed heads, fp32 v) ----------
__global__ void __launch_bounds__(128) band_kernel(const float* __restrict__ v,
                                                   __half* __restrict__ z)
{
    const int p  = threadIdx.x;          // 0..127
    const int q0 = blockIdx.x * 32;
    const int hp = blockIdx.y;           // 0..5
    const int b  = blockIdx.z;

    const float* vp = v + (size_t)b * L_SEQ * NPK + hp * 128 + p;
    const int c_ = hp * 128 + p;
    const int qq_ = (c_ >> 1) & 31;
    const int pp  = ppmap(qq_);
    const int pc  = (c_ & ~63) + pp * 2 + (c_ & 1);
    __half* zp = z + ((size_t)(b * L_SEQ + q0)) * NPK + pc;

    const int m3 = hp % 3;
    const int sh = (m3 == 0) ? 0 : ((m3 == 1) ? -1 : 1);
    const int cb = q0 + sh;

    float r[15];
    #pragma unroll
    for (int i = 0; i < 15; i++) {
        int j = cb - 7 + i;
        r[i] = (j >= 0 && j < L_SEQ) ? vp[(size_t)j * NPK] : 0.f;
    }

    #pragma unroll
    for (int qq = 0; qq < 32; qq++) {
        const int c = cb + qq;
        float acc = 0.f, Z = 0.f;
        #pragma unroll
        for (int i = 0; i < 15; i++) {
            int j = c - 7 + i;
            if (j >= 0 && j < L_SEQ) { Z += WTC[i]; acc += WTC[i] * r[(i + qq) % 15]; }
        }
        zp[(size_t)qq * NPK] = __float2half_rn(acc / Z);
        int jn = c + 8;
        r[qq % 15] = (jn >= 0 && jn < L_SEQ) ? vp[(size_t)jn * NPK] : 0.f;
    }
}

// ---------------- heads 3/4 constant path (fp32 exact) ----------
// Step 1: xw[b,h,:] = sum_jj (w_jj / Z) * x[b, j(jj), :]
// grid (8, NB), 32 threads: e4 = blockIdx.x*32 + tid.  Same per-thread
// summation order as before -> bit-identical xw; 8x more SMs cover latency.
__global__ void __launch_bounds__(32) xw_kernel(const float* __restrict__ x,
                                                float* __restrict__ xw)
{
    const int b  = blockIdx.y;
    const int e4 = blockIdx.x * 32 + threadIdx.x;   // float4 index 0..255
    float Z = 0.f;
    #pragma unroll
    for (int i = 0; i < 8; i++) Z += WTC[7 + i];
    const float inz = 1.f / Z;

    const float4* xb = (const float4*)(x + (size_t)b * L_SEQ * EMB);
    float4 s0 = make_float4(0.f, 0.f, 0.f, 0.f);
    float4 s1 = make_float4(0.f, 0.f, 0.f, 0.f);
    #pragma unroll
    for (int jj = 0; jj < 8; jj++) {
        float w0 = WTC[7 + jj] * inz;
        float4 a = xb[(size_t)jj * 256 + e4];
        s0.x += w0 * a.x; s0.y += w0 * a.y; s0.z += w0 * a.z; s0.w += w0 * a.w;
        float w1 = WTC[jj] * inz;
        float4 d = xb[(size_t)(L_SEQ - 8 + jj) * 256 + e4];
        s1.x += w1 * d.x; s1.y += w1 * d.y; s1.z += w1 * d.z; s1.w += w1 * d.w;
    }
    ((float4*)(xw + (size_t)b * 2 * EMB))[e4]       = s0;
    ((float4*)(xw + (size_t)b * 2 * EMB + EMB))[e4] = s1;
}

// Step 2: zc[b,c] = xw[b, h(c), :] . W_in[384+c, :]  (h = c>=128)
__global__ void __launch_bounds__(256) zc_kernel(const float* __restrict__ xw,
                                                 const float* __restrict__ Win,
                                                 float* __restrict__ zc)
{
    const int gw   = blockIdx.x * 8 + (threadIdx.x >> 5);  // global warp 0..2047
    const int lane = threadIdx.x & 31;
    const int c = gw & 255;
    const int b = gw >> 8;
    const int h = (c >> 7) & 1;

    const float4* xr = (const float4*)(xw + ((size_t)b * 2 + h) * EMB);
    const float4* wr = (const float4*)(Win + (size_t)(384 + c) * EMB);
    float s = 0.f;
    #pragma unroll
    for (int i = 0; i < 8; i++) {
        float4 a = xr[lane + i * 32];
        float4 w = wr[lane + i * 32];
        s += a.x * w.x + a.y * w.y + a.z * w.z + a.w * w.w;
    }
    #pragma unroll
    for (int o = 16; o > 0; o >>= 1) s += __shfl_down_sync(0xffffffffu, s, o);
    if (lane == 0) zc[(size_t)b * 256 + c] = s;
}

// Step 3: bias[b, n] = sum_c zc[b,c] * W_out[n, 384+c]  -- warp per output
__global__ void __launch_bounds__(256) bias_kernel(const float* __restrict__ zc,
                                                   const float* __restrict__ Wout,
                                                   float* __restrict__ bias)
{
    const int gw   = blockIdx.x * 8 + (threadIdx.x >> 5);  // 0..8191
    const int lane = threadIdx.x & 31;
    const int n = gw & 1023;
    const int b = gw >> 10;

    const float4* zr = (const float4*)(zc + (size_t)b * 256);
    const float4* wr = (const float4*)(Wout + (size_t)n * EMB + 384);
    float s = 0.f;
    #pragma unroll
    for (int i = 0; i < 2; i++) {
        float4 zv = zr[lane + i * 32];
        float4 wv = wr[lane + i * 32];
        s += zv.x * wv.x + zv.y * wv.y + zv.z * wv.z + zv.w * wv.w;
    }
    #pragma unroll
    for (int o = 16; o > 0; o >>= 1) s += __shfl_down_sync(0xffffffffu, s, o);
    if (lane == 0) bias[(size_t)b * EMB + n] = s;
}

// ---------------- launch ----------------
extern "C" void kernel_launch(void* const* d_in, const int* in_sizes, int n_in,
                              void* d_out, int out_size)
{
    const float* x   = (const float*)d_in[0];
    const float* Win = (const float*)d_in[1];
    const float* Wou = (const float*)d_in[2];
    float* out = (float*)d_out;

    __half *xt, *w1, *w2, *z;
    float *v, *xw, *zc, *bias;
    cudaGetSymbolAddress((void**)&xt,  g_xt);
    cudaGetSymbolAddress((void**)&w1,  g_w1);
    cudaGetSymbolAddress((void**)&w2,  g_w2);
    cudaGetSymbolAddress((void**)&v,   g_v);
    cudaGetSymbolAddress((void**)&z,   g_z);
    cudaGetSymbolAddress((void**)&xw,  g_xw);
    cudaGetSymbolAddress((void**)&zc,  g_zc);
    cudaGetSymbolAddress((void**)&bias,g_bias);

    cudaFuncSetAttribute(gemm_f16_t<1024, NPK, false>,
                         cudaFuncAttributeMaxDynamicSharedMemorySize, GSMEM);
    cudaFuncSetAttribute(gemm_f16_t<NPK, 1024, true>,
                         cudaFuncAttributeMaxDynamicSharedMemorySize, GSMEM);

    const int nx4  = (MTOT * EMB) / 4;
    const int nw14 = (NPK * EMB) / 4;
    const int nw24 = (EMB * NPK) / 4;
    cvt_perm_h<<<(nx4  + 255) / 256, 256>>>(x,   xt, nx4);
    cvt_w1p  <<<(nw14 + 255) / 256, 256>>>(Win, w1, nw14);
    cvt_w2p  <<<(nw24 + 255) / 256, 256>>>(Wou, w2, nw24);

    // heads 3/4 constant path (fp32 exact, tiny)
    xw_kernel  <<<dim3(8, NB), 32>>>(x, xw);
    zc_kernel  <<<256, 256>>>(xw, Win, zc);
    bias_kernel<<<1024, 256>>>(zc, Wou, bias);

    // main path (6 packed heads)
    gemm_f16_t<1024, NPK, false><<<dim3(NPK / BN, MTOT / BM), 512, GSMEM>>>(xt, w1, v, nullptr);
    band_kernel<<<dim3(L_SEQ / 32, 6, NB), 128>>>(v, z);
    gemm_f16_t<NPK, 1024, true><<<dim3(EMB / BN, MTOT / BM), 512, GSMEM>>>(z, w2, out, bias);
}